// round 2
// baseline (speedup 1.0000x reference)
#include <cuda_runtime.h>

#define NN 100000
#define NE 600000
#define DI 128
#define DH 128
#define NC 64

// Scratch (device globals -- no allocation allowed)
__device__ __align__(16) float g_nbr1[(size_t)NN * DI];   // layer-1 neighbor sums
__device__ __align__(16) float g_nbr2[(size_t)NN * DH];   // layer-2 neighbor sums
__device__ __align__(16) float g_h1[(size_t)NN * DH];     // layer-1 activations
__device__ __align__(16) float g_deg[NN];                 // in-degree (float)

// ---------------------------------------------------------------------------
// Zero the accumulators (buffers must be zero at start of every replay)
// ---------------------------------------------------------------------------
__global__ void zero_kernel() {
    const int n1 = NN * DI / 4;           // 3.2M float4 per nbr buffer
    const int nd = NN / 4;                // 25K float4 for deg
    int i = blockIdx.x * blockDim.x + threadIdx.x;
    float4 z = make_float4(0.f, 0.f, 0.f, 0.f);
    if (i < n1)                ((float4*)g_nbr1)[i] = z;
    else if (i < 2 * n1)       ((float4*)g_nbr2)[i - n1] = z;
    else if (i < 2 * n1 + nd)  ((float4*)g_deg)[i - 2 * n1] = z;
}

// ---------------------------------------------------------------------------
// Edge scatter: warp per edge, 128 floats as 32 x float4 vector reductions.
// layer==0: feat = x  -> g_nbr1 (+deg);  layer==1: feat = g_h1 -> g_nbr2
// ---------------------------------------------------------------------------
__global__ void scatter_kernel(const float* __restrict__ x_ext,
                               const int* __restrict__ src,
                               const int* __restrict__ dst,
                               int layer) {
    int gw = (blockIdx.x * blockDim.x + threadIdx.x) >> 5;
    if (gw >= NE) return;
    int lane = threadIdx.x & 31;
    const float* feat = layer ? g_h1 : x_ext;
    float* outbuf     = layer ? g_nbr2 : g_nbr1;

    int s = __ldg(src + gw);
    int d = __ldg(dst + gw);
    float4 v = ((const float4*)feat)[(size_t)s * 32 + lane];
    float4* p = ((float4*)outbuf) + (size_t)d * 32 + lane;
    asm volatile("red.global.add.v4.f32 [%0], {%1, %2, %3, %4};"
                 :: "l"(p), "f"(v.x), "f"(v.y), "f"(v.z), "f"(v.w)
                 : "memory");
    if (layer == 0 && lane == 0) atomicAdd(&g_deg[d], 1.0f);
}

// ---------------------------------------------------------------------------
// Layer 1: h1 = relu(x @ Wself + (nbr1/max(deg,1)) @ Wneigh + b1)
// 256 threads, M-tile 64, N=128, K=2x128 (two phases). W resident in SMEM.
// Thread tile 4 (M) x 8 (N).
// SMEM: Ws 64KB + Wn 64KB + A_T 32KB = 160KB
// ---------------------------------------------------------------------------
__global__ void gemm1_kernel(const float* __restrict__ x,
                             const float* __restrict__ Wself,
                             const float* __restrict__ Wneigh,
                             const float* __restrict__ bias) {
    extern __shared__ float sm[];
    float* Ws = sm;                 // [128][128]
    float* Wn = sm + DI * DH;       // [128][128]
    float* As = sm + 2 * DI * DH;   // [128][64] (K-major, transposed A tile)

    int tid = threadIdx.x;
    // Load both weight matrices into SMEM (once per block)
    {
        const float4* s4 = (const float4*)Wself;
        const float4* n4 = (const float4*)Wneigh;
        float4* ws4 = (float4*)Ws;
        float4* wn4 = (float4*)Wn;
        for (int i = tid; i < DI * DH / 4; i += 256) { ws4[i] = s4[i]; wn4[i] = n4[i]; }
    }
    int ty = tid >> 4;      // 0..15 -> rows ty*4 .. ty*4+3
    int tx = tid & 15;      // 0..15 -> cols tx*8 .. tx*8+7
    float bb[8];
    #pragma unroll
    for (int j = 0; j < 8; j++) bb[j] = __ldg(bias + (tx << 3) + j);

    const int nTiles = (NN + 63) / 64;
    for (int tile = blockIdx.x; tile < nTiles; tile += gridDim.x) {
        int base = tile * 64;
        float acc[4][8];
        #pragma unroll
        for (int r = 0; r < 4; r++)
            #pragma unroll
            for (int j = 0; j < 8; j++) acc[r][j] = 0.f;

        #pragma unroll
        for (int ph = 0; ph < 2; ++ph) {
            __syncthreads();   // prev compute done (and W load visible, iter 0)
            // load A tile (transposed): As[k][node_local]
            {
                const float* feat = ph ? g_nbr1 : x;
                int nl = tid & 63;
                int cs = (tid >> 6) << 5;      // 0,32,64,96
                int node = base + nl;
                bool valid = node < NN;
                float scale = 1.0f;
                if (ph) {
                    float dg = valid ? g_deg[node] : 1.0f;
                    scale = 1.0f / fmaxf(dg, 1.0f);
                }
                const float4* row = (const float4*)(feat + (size_t)node * DI);
                #pragma unroll
                for (int i = 0; i < 8; i++) {
                    int c = cs + i * 4;
                    float4 v = make_float4(0.f, 0.f, 0.f, 0.f);
                    if (valid) v = row[c >> 2];
                    As[(c + 0) * 64 + nl] = v.x * scale;
                    As[(c + 1) * 64 + nl] = v.y * scale;
                    As[(c + 2) * 64 + nl] = v.z * scale;
                    As[(c + 3) * 64 + nl] = v.w * scale;
                }
            }
            __syncthreads();
            const float* W = ph ? Wn : Ws;
            #pragma unroll 4
            for (int k = 0; k < 128; ++k) {
                float4 a  = *(const float4*)(As + k * 64 + (ty << 2));
                float4 b0 = *(const float4*)(W + k * DH + (tx << 3));
                float4 b1 = *(const float4*)(W + k * DH + (tx << 3) + 4);
                float av[4] = {a.x, a.y, a.z, a.w};
                float bv[8] = {b0.x, b0.y, b0.z, b0.w, b1.x, b1.y, b1.z, b1.w};
                #pragma unroll
                for (int r = 0; r < 4; r++)
                    #pragma unroll
                    for (int j = 0; j < 8; j++)
                        acc[r][j] = fmaf(av[r], bv[j], acc[r][j]);
            }
        }
        // epilogue: bias + relu, store to g_h1
        #pragma unroll
        for (int r = 0; r < 4; r++) {
            int node = base + (ty << 2) + r;
            if (node < NN) {
                float* o = g_h1 + (size_t)node * DH + (tx << 3);
                float4 o0, o1;
                o0.x = fmaxf(acc[r][0] + bb[0], 0.f);
                o0.y = fmaxf(acc[r][1] + bb[1], 0.f);
                o0.z = fmaxf(acc[r][2] + bb[2], 0.f);
                o0.w = fmaxf(acc[r][3] + bb[3], 0.f);
                o1.x = fmaxf(acc[r][4] + bb[4], 0.f);
                o1.y = fmaxf(acc[r][5] + bb[5], 0.f);
                o1.z = fmaxf(acc[r][6] + bb[6], 0.f);
                o1.w = fmaxf(acc[r][7] + bb[7], 0.f);
                *(float4*)o       = o0;
                *(float4*)(o + 4) = o1;
            }
        }
    }
}

// ---------------------------------------------------------------------------
// Layer 2: out = h1 @ Wself2 + (nbr2/max(deg,1)) @ Wneigh2 + b2
// M-tile 64, N=64, K=2x128. Thread tile 4x4. SMEM 96KB.
// ---------------------------------------------------------------------------
__global__ void gemm2_kernel(const float* __restrict__ Wself,
                             const float* __restrict__ Wneigh,
                             const float* __restrict__ bias,
                             float* __restrict__ out) {
    extern __shared__ float sm[];
    float* Ws = sm;                 // [128][64]
    float* Wn = sm + DH * NC;       // [128][64]
    float* As = sm + 2 * DH * NC;   // [128][64]

    int tid = threadIdx.x;
    {
        const float4* s4 = (const float4*)Wself;
        const float4* n4 = (const float4*)Wneigh;
        float4* ws4 = (float4*)Ws;
        float4* wn4 = (float4*)Wn;
        for (int i = tid; i < DH * NC / 4; i += 256) { ws4[i] = s4[i]; wn4[i] = n4[i]; }
    }
    int ty = tid >> 4;
    int tx = tid & 15;
    float bb[4];
    #pragma unroll
    for (int j = 0; j < 4; j++) bb[j] = __ldg(bias + (tx << 2) + j);

    const int nTiles = (NN + 63) / 64;
    for (int tile = blockIdx.x; tile < nTiles; tile += gridDim.x) {
        int base = tile * 64;
        float acc[4][4];
        #pragma unroll
        for (int r = 0; r < 4; r++)
            #pragma unroll
            for (int j = 0; j < 4; j++) acc[r][j] = 0.f;

        #pragma unroll
        for (int ph = 0; ph < 2; ++ph) {
            __syncthreads();
            {
                const float* feat = ph ? g_nbr2 : g_h1;
                int nl = tid & 63;
                int cs = (tid >> 6) << 5;
                int node = base + nl;
                bool valid = node < NN;
                float scale = 1.0f;
                if (ph) {
                    float dg = valid ? g_deg[node] : 1.0f;
                    scale = 1.0f / fmaxf(dg, 1.0f);
                }
                const float4* row = (const float4*)(feat + (size_t)node * DH);
                #pragma unroll
                for (int i = 0; i < 8; i++) {
                    int c = cs + i * 4;
                    float4 v = make_float4(0.f, 0.f, 0.f, 0.f);
                    if (valid) v = row[c >> 2];
                    As[(c + 0) * 64 + nl] = v.x * scale;
                    As[(c + 1) * 64 + nl] = v.y * scale;
                    As[(c + 2) * 64 + nl] = v.z * scale;
                    As[(c + 3) * 64 + nl] = v.w * scale;
                }
            }
            __syncthreads();
            const float* W = ph ? Wn : Ws;
            #pragma unroll 4
            for (int k = 0; k < 128; ++k) {
                float4 a = *(const float4*)(As + k * 64 + (ty << 2));
                float4 b = *(const float4*)(W + k * NC + (tx << 2));
                float av[4] = {a.x, a.y, a.z, a.w};
                float bv[4] = {b.x, b.y, b.z, b.w};
                #pragma unroll
                for (int r = 0; r < 4; r++)
                    #pragma unroll
                    for (int j = 0; j < 4; j++)
                        acc[r][j] = fmaf(av[r], bv[j], acc[r][j]);
            }
        }
        #pragma unroll
        for (int r = 0; r < 4; r++) {
            int node = base + (ty << 2) + r;
            if (node < NN) {
                float4 o0;
                o0.x = acc[r][0] + bb[0];
                o0.y = acc[r][1] + bb[1];
                o0.z = acc[r][2] + bb[2];
                o0.w = acc[r][3] + bb[3];
                *(float4*)(out + (size_t)node * NC + (tx << 2)) = o0;
            }
        }
    }
}

// ---------------------------------------------------------------------------
extern "C" void kernel_launch(void* const* d_in, const int* in_sizes, int n_in,
                              void* d_out, int out_size) {
    const float* x    = (const float*)d_in[0];
    const int*   src  = (const int*)d_in[1];
    const int*   dst  = (const int*)d_in[2];
    const float* Ws1  = (const float*)d_in[3];
    const float* Wn1  = (const float*)d_in[4];
    const float* b1   = (const float*)d_in[5];
    const float* Ws2  = (const float*)d_in[6];
    const float* Wn2  = (const float*)d_in[7];
    const float* b2   = (const float*)d_in[8];
    float* out = (float*)d_out;

    const int SMEM1 = (2 * DI * DH + 128 * 64) * 4;   // 163840 B
    const int SMEM2 = (2 * DH * NC + 128 * 64) * 4;   //  98304 B
    cudaFuncSetAttribute(gemm1_kernel, cudaFuncAttributeMaxDynamicSharedMemorySize, SMEM1);
    cudaFuncSetAttribute(gemm2_kernel, cudaFuncAttributeMaxDynamicSharedMemorySize, SMEM2);

    // 1) zero accumulators + degree
    {
        int total4 = 2 * (NN * DI / 4) + NN / 4;
        int grid = (total4 + 255) / 256;
        zero_kernel<<<grid, 256>>>();
    }
    // 2) layer-1 scatter (+ degree)
    scatter_kernel<<<(NE * 32 + 255) / 256, 256>>>(x, src, dst, 0);
    // 3) layer-1 fused GEMM -> g_h1
    gemm1_kernel<<<608, 256, SMEM1>>>(x, Ws1, Wn1, b1);
    // 4) layer-2 scatter
    scatter_kernel<<<(NE * 32 + 255) / 256, 256>>>(x, src, dst, 1);
    // 5) layer-2 fused GEMM -> out
    gemm2_kernel<<<608, 256, SMEM2>>>(Ws2, Wn2, b2, out);
}

// round 6
// speedup vs baseline: 1.0373x; 1.0373x over previous
#include <cuda_runtime.h>

#define NN 100000
#define NE 600000
#define DI 128
#define DH 128
#define NC 64

// Scratch (device globals -- referenced ONLY inside kernels, never from host)
__device__ __align__(16) float g_nbr1[(size_t)NN * DI];   // layer-1 neighbor sums (128-wide)
__device__ __align__(16) float g_h1[(size_t)NN * DH];     // layer-1 activations
__device__ __align__(16) float g_p[(size_t)NN * NC];      // h1 @ Wn2 (pre-projected, 64-wide)
__device__ __align__(16) float g_nbr2[(size_t)NN * NC];   // layer-2 neighbor sums (64-wide)
__device__ float g_deg[NN];                               // in-degree (float)

// ---------------- packed f32x2 helpers (sm_103a FFMA2) ----------------
__device__ __forceinline__ unsigned long long dup2(float x) {
    unsigned long long r;
    asm("mov.b64 %0, {%1, %1};" : "=l"(r) : "f"(x));
    return r;
}
__device__ __forceinline__ void ffma2(unsigned long long& d,
                                      unsigned long long a, unsigned long long b) {
    asm("fma.rn.f32x2 %0, %1, %2, %0;" : "+l"(d) : "l"(a), "l"(b));
}
__device__ __forceinline__ float2 unpk(unsigned long long v) {
    float2 f;
    asm("mov.b64 {%0, %1}, %2;" : "=f"(f.x), "=f"(f.y) : "l"(v));
    return f;
}

// ---------------------------------------------------------------------------
// Zero the accumulators (buffers must be zero at start of every replay)
// ---------------------------------------------------------------------------
__global__ void zero_kernel() {
    const int n1 = NN * DI / 4;
    const int n2 = NN * NC / 4;
    const int nd = NN / 4;
    int i = blockIdx.x * blockDim.x + threadIdx.x;
    float4 z = make_float4(0.f, 0.f, 0.f, 0.f);
    if (i < n1)                 ((float4*)g_nbr1)[i] = z;
    else if (i < n1 + n2)       ((float4*)g_nbr2)[i - n1] = z;
    else if (i < n1 + n2 + nd)  ((float4*)g_deg)[i - n1 - n2] = z;
}

// ---------------------------------------------------------------------------
// Layer-1 edge scatter: warp per edge, 128 floats as 32 x float4 REDG, + degree
// ---------------------------------------------------------------------------
__global__ void scatter1_kernel(const float* __restrict__ x,
                                const int* __restrict__ src,
                                const int* __restrict__ dst) {
    int gw = (blockIdx.x * blockDim.x + threadIdx.x) >> 5;
    if (gw >= NE) return;
    int lane = threadIdx.x & 31;
    int s = __ldg(src + gw);
    int d = __ldg(dst + gw);
    float4 v = ((const float4*)x)[(size_t)s * 32 + lane];
    float4* p = ((float4*)g_nbr1) + (size_t)d * 32 + lane;
    asm volatile("red.global.add.v4.f32 [%0], {%1, %2, %3, %4};"
                 :: "l"(p), "f"(v.x), "f"(v.y), "f"(v.z), "f"(v.w)
                 : "memory");
    if (lane == 0) atomicAdd(&g_deg[d], 1.0f);
}

// ---------------------------------------------------------------------------
// Layer-2 edge scatter of pre-projected g_p (64-wide): HALF-warp per edge.
// ---------------------------------------------------------------------------
__global__ void scatter2_kernel(const int* __restrict__ src,
                                const int* __restrict__ dst) {
    int gw = (blockIdx.x * blockDim.x + threadIdx.x) >> 5;
    int lane = threadIdx.x & 31;
    int e = gw * 2 + (lane >> 4);
    if (e >= NE) return;
    int l16 = lane & 15;
    int s = __ldg(src + e);
    int d = __ldg(dst + e);
    float4 v = ((const float4*)g_p)[(size_t)s * 16 + l16];
    float4* p = ((float4*)g_nbr2) + (size_t)d * 16 + l16;
    asm volatile("red.global.add.v4.f32 [%0], {%1, %2, %3, %4};"
                 :: "l"(p), "f"(v.x), "f"(v.y), "f"(v.z), "f"(v.w)
                 : "memory");
}

// ---------------------------------------------------------------------------
// Layer 1: h1 = relu(x @ Wself + (nbr1/max(deg,1)) @ Wneigh + b1)
// R2-proven shell (M-tile 64, N=128, K=2x128, SMEM 160KB); FFMA2 inner loop.
// Thread tile 4(M)=2 pairs x 8(N). Reads g_nbr1/g_deg, writes g_h1 internally.
// ---------------------------------------------------------------------------
__global__ void __launch_bounds__(256)
gemm1_kernel(const float* __restrict__ x,
             const float* __restrict__ Ws_g,
             const float* __restrict__ Wn_g,
             const float* __restrict__ bias) {
    extern __shared__ float sm[];
    float* Ws = sm;                 // [128][128]
    float* Wn = sm + DI * DH;       // [128][128]
    float* As = sm + 2 * DI * DH;   // [128 k][64 m]

    int tid = threadIdx.x;
    {
        const float4* s4 = (const float4*)Ws_g;
        const float4* n4 = (const float4*)Wn_g;
        float4* ws4 = (float4*)Ws;
        float4* wn4 = (float4*)Wn;
        for (int i = tid; i < DI * DH / 4; i += 256) { ws4[i] = s4[i]; wn4[i] = n4[i]; }
    }
    int ty = tid >> 4;      // rows ty*4 .. ty*4+3 (2 pairs)
    int tx = tid & 15;      // cols tx*8 .. tx*8+7
    float bb[8];
    #pragma unroll
    for (int j = 0; j < 8; j++) bb[j] = __ldg(bias + (tx << 3) + j);

    const int nTiles = (NN + 63) / 64;
    for (int tile = blockIdx.x; tile < nTiles; tile += gridDim.x) {
        int base = tile * 64;
        unsigned long long acc[2][8];
        #pragma unroll
        for (int pr = 0; pr < 2; pr++)
            #pragma unroll
            for (int j = 0; j < 8; j++) acc[pr][j] = 0ull;

        #pragma unroll
        for (int ph = 0; ph < 2; ++ph) {
            __syncthreads();
            {   // A-tile loader (verbatim from passing R2 kernel)
                const float* feat = ph ? g_nbr1 : x;
                int nl = tid & 63;
                int cs = (tid >> 6) << 5;      // 0,32,64,96
                int node = base + nl;
                bool valid = node < NN;
                float scale = 1.0f;
                if (ph) {
                    float dg = valid ? g_deg[node] : 1.0f;
                    scale = 1.0f / fmaxf(dg, 1.0f);
                }
                const float4* row = (const float4*)(feat + (size_t)node * DI);
                #pragma unroll
                for (int i = 0; i < 8; i++) {
                    int c = cs + i * 4;
                    float4 v = make_float4(0.f, 0.f, 0.f, 0.f);
                    if (valid) v = row[c >> 2];
                    As[(c + 0) * 64 + nl] = v.x * scale;
                    As[(c + 1) * 64 + nl] = v.y * scale;
                    As[(c + 2) * 64 + nl] = v.z * scale;
                    As[(c + 3) * 64 + nl] = v.w * scale;
                }
            }
            __syncthreads();
            const float* W = ph ? Wn : Ws;
            #pragma unroll 4
            for (int k = 0; k < 128; ++k) {
                ulonglong2 a = *(const ulonglong2*)(As + k * 64 + (ty << 2));
                float4 b0 = *(const float4*)(W + k * DH + (tx << 3));
                float4 b1 = *(const float4*)(W + k * DH + (tx << 3) + 4);
                unsigned long long ap[2] = {a.x, a.y};
                unsigned long long bd[8] = {dup2(b0.x), dup2(b0.y), dup2(b0.z), dup2(b0.w),
                                            dup2(b1.x), dup2(b1.y), dup2(b1.z), dup2(b1.w)};
                #pragma unroll
                for (int pr = 0; pr < 2; pr++)
                    #pragma unroll
                    for (int j = 0; j < 8; j++)
                        ffma2(acc[pr][j], ap[pr], bd[j]);
            }
        }
        // epilogue: bias + relu, store to g_h1
        #pragma unroll
        for (int pr = 0; pr < 2; pr++) {
            float2 v[8];
            #pragma unroll
            for (int j = 0; j < 8; j++) v[j] = unpk(acc[pr][j]);
            #pragma unroll
            for (int half = 0; half < 2; half++) {
                int r = base + (ty << 2) + pr * 2 + half;
                if (r < NN) {
                    float* o = g_h1 + (size_t)r * DH + (tx << 3);
                    float e0 = half ? v[0].y : v[0].x;
                    float e1 = half ? v[1].y : v[1].x;
                    float e2 = half ? v[2].y : v[2].x;
                    float e3 = half ? v[3].y : v[3].x;
                    float e4 = half ? v[4].y : v[4].x;
                    float e5 = half ? v[5].y : v[5].x;
                    float e6 = half ? v[6].y : v[6].x;
                    float e7 = half ? v[7].y : v[7].x;
                    float4 o0, o1;
                    o0.x = fmaxf(e0 + bb[0], 0.f); o0.y = fmaxf(e1 + bb[1], 0.f);
                    o0.z = fmaxf(e2 + bb[2], 0.f); o0.w = fmaxf(e3 + bb[3], 0.f);
                    o1.x = fmaxf(e4 + bb[4], 0.f); o1.y = fmaxf(e5 + bb[5], 0.f);
                    o1.z = fmaxf(e6 + bb[6], 0.f); o1.w = fmaxf(e7 + bb[7], 0.f);
                    *(float4*)o = o0; *(float4*)(o + 4) = o1;
                }
            }
        }
    }
}

// ---------------------------------------------------------------------------
// N=64 single-phase GEMM. A = g_h1 (internal, device symbol).
//   mode==0: g_p  = g_h1 @ W                      (pre-projection)
//   mode==1: out_ext = g_h1 @ W + bias + nbr2/deg (final layer, d_out)
// FFMA2 inner loop, M-tile 64, K=128, thread tile 4x4. SMEM 64KB.
// ---------------------------------------------------------------------------
__global__ void __launch_bounds__(256)
gemm64_kernel(const float* __restrict__ Wg,
              const float* __restrict__ bias,
              float* __restrict__ out_ext,
              int mode) {
    extern __shared__ float sm[];
    float* W = sm;                  // [128][64]
    float* As = sm + DH * NC;       // [128 k][64 m]

    const float* A = g_h1;
    float* out = mode ? out_ext : g_p;

    int tid = threadIdx.x;
    {
        const float4* w4 = (const float4*)Wg;
        float4* ws4 = (float4*)W;
        for (int i = tid; i < DH * NC / 4; i += 256) ws4[i] = w4[i];
    }
    int ty = tid >> 4;      // rows ty*4 (2 pairs)
    int tx = tid & 15;      // cols tx*4
    float4 bb = make_float4(0.f, 0.f, 0.f, 0.f);
    if (mode) bb = *(const float4*)(bias + (tx << 2));

    const int nTiles = (NN + 63) / 64;
    for (int tile = blockIdx.x; tile < nTiles; tile += gridDim.x) {
        int base = tile * 64;
        unsigned long long acc[2][4];
        #pragma unroll
        for (int pr = 0; pr < 2; pr++)
            #pragma unroll
            for (int j = 0; j < 4; j++) acc[pr][j] = 0ull;

        __syncthreads();
        {   // A-tile loader (proven pattern; rows are DH=128 wide)
            int nl = tid & 63;
            int cs = (tid >> 6) << 5;
            int node = base + nl;
            bool valid = node < NN;
            const float4* row = (const float4*)(A + (size_t)node * DH);
            #pragma unroll
            for (int i = 0; i < 8; i++) {
                int c = cs + i * 4;
                float4 v = make_float4(0.f, 0.f, 0.f, 0.f);
                if (valid) v = row[c >> 2];
                As[(c + 0) * 64 + nl] = v.x;
                As[(c + 1) * 64 + nl] = v.y;
                As[(c + 2) * 64 + nl] = v.z;
                As[(c + 3) * 64 + nl] = v.w;
            }
        }
        __syncthreads();
        #pragma unroll 4
        for (int k = 0; k < 128; ++k) {
            ulonglong2 a = *(const ulonglong2*)(As + k * 64 + (ty << 2));
            float4 b = *(const float4*)(W + k * NC + (tx << 2));
            unsigned long long ap[2] = {a.x, a.y};
            unsigned long long bd[4] = {dup2(b.x), dup2(b.y), dup2(b.z), dup2(b.w)};
            #pragma unroll
            for (int pr = 0; pr < 2; pr++)
                #pragma unroll
                for (int j = 0; j < 4; j++)
                    ffma2(acc[pr][j], ap[pr], bd[j]);
        }
        // epilogue
        #pragma unroll
        for (int pr = 0; pr < 2; pr++) {
            float2 v[4];
            #pragma unroll
            for (int j = 0; j < 4; j++) v[j] = unpk(acc[pr][j]);
            #pragma unroll
            for (int half = 0; half < 2; half++) {
                int r = base + (ty << 2) + pr * 2 + half;
                if (r < NN) {
                    float e0 = half ? v[0].y : v[0].x;
                    float e1 = half ? v[1].y : v[1].x;
                    float e2 = half ? v[2].y : v[2].x;
                    float e3 = half ? v[3].y : v[3].x;
                    float4 o;
                    if (mode) {
                        float inv = 1.0f / fmaxf(g_deg[r], 1.0f);
                        float4 nv = ((const float4*)g_nbr2)[(size_t)r * 16 + tx];
                        o.x = e0 + bb.x + nv.x * inv;
                        o.y = e1 + bb.y + nv.y * inv;
                        o.z = e2 + bb.z + nv.z * inv;
                        o.w = e3 + bb.w + nv.w * inv;
                    } else {
                        o.x = e0; o.y = e1; o.z = e2; o.w = e3;
                    }
                    *(float4*)(out + (size_t)r * NC + (tx << 2)) = o;
                }
            }
        }
    }
}

// ---------------------------------------------------------------------------
extern "C" void kernel_launch(void* const* d_in, const int* in_sizes, int n_in,
                              void* d_out, int out_size) {
    const float* x    = (const float*)d_in[0];
    const int*   src  = (const int*)d_in[1];
    const int*   dst  = (const int*)d_in[2];
    const float* Ws1  = (const float*)d_in[3];
    const float* Wn1  = (const float*)d_in[4];
    const float* b1   = (const float*)d_in[5];
    const float* Ws2  = (const float*)d_in[6];
    const float* Wn2  = (const float*)d_in[7];
    const float* b2   = (const float*)d_in[8];
    float* out = (float*)d_out;

    const int SMEM1 = (2 * DI * DH + 128 * 64) * 4;   // 163840 B (160KB, proven)
    const int SMEM2 = (DH * NC + 128 * 64) * 4;       //  65536 B (64KB)
    cudaFuncSetAttribute(gemm1_kernel,  cudaFuncAttributeMaxDynamicSharedMemorySize, SMEM1);
    cudaFuncSetAttribute(gemm64_kernel, cudaFuncAttributeMaxDynamicSharedMemorySize, SMEM2);

    // 1) zero accumulators + degree
    {
        int total4 = NN * DI / 4 + NN * NC / 4 + NN / 4;
        zero_kernel<<<(total4 + 255) / 256, 256>>>();
    }
    // 2) layer-1 scatter (+ degree), warp per edge
    scatter1_kernel<<<(NE * 32 + 255) / 256, 256>>>(x, src, dst);
    // 3) layer-1 fused GEMM -> g_h1 (internal)
    gemm1_kernel<<<608, 256, SMEM1>>>(x, Ws1, Wn1, b1);
    // 4) pre-project: g_p = g_h1 @ Wn2 (all internal; only W passed)
    gemm64_kernel<<<608, 256, SMEM2>>>(Wn2, b2, out, 0);
    // 5) layer-2 scatter of g_p (64-wide, half-warp per edge)
    scatter2_kernel<<<(NE / 2 * 32 + 255) / 256, 256>>>(src, dst);
    // 6) out = g_h1 @ Ws2 + b2 + nbr2/deg
    gemm64_kernel<<<608, 256, SMEM2>>>(Ws2, b2, out, 1);
}